// round 10
// baseline (speedup 1.0000x reference)
#include <cuda_runtime.h>
#include <math.h>

#define KS   18       // k-splits (grid 288 -> 2 CTAs/SM)
#define DC   128      // d-chunk staged per iteration
#define STR  132      // smem row stride (floats): conflict-free both phases
#define NQ   200
#define NGT  32
#define DTOT 65536
#define CHTOT (DTOT/DC)   // 512 chunks along d

// ---- scratch (static __device__, per allocation rules) ----
__device__ float g_part[KS * 4 * NQ * NGT];   // per-ksplit partial inter
__device__ float g_psum[KS * 4 * NQ];         // per-ksplit sigmoid row sums
__device__ float g_gtp[KS * 4 * NGT];         // per-ksplit gt row sums
__device__ float g_comb[4 * NQ * NGT];        // combined scores

__device__ __forceinline__ float sigf(float x) {
    return __fdividef(1.0f, 1.0f + __expf(-x));
}
__device__ __forceinline__ void ffma2(unsigned long long& d,
                                      unsigned long long a,
                                      unsigned long long b) {
    asm("fma.rn.f32x2 %0, %1, %2, %0;" : "+l"(d) : "l"(a), "l"(b));
}

extern __shared__ float sm[];

// ---------------------------------------------------------------------------
// Kernel A: sigmoid + K-split GEMM + fused row sums.
// grid(KS, 4 qtiles, 4 batches), 256 thr, 2 CTAs/SM.
// Warp w: wd = w&1 (d-half, 64 d), wq = (w>>1)&1 (q-half, 32 q),
//         wn = w>>2 (n-half, 16 n). Lanes: qtr = lane&7, ntr = lane>>3.
// Per-thread 4q x 4n f32x2 accumulators (32 regs). Register prefetch.
// ---------------------------------------------------------------------------
__global__ void __launch_bounds__(256, 2)
kA(const float* __restrict__ pm, const float* __restrict__ gt) {
    const int ks = blockIdx.x, qt = blockIdx.y, b = blockIdx.z;
    const int q0 = qt * 64;
    const int tid = threadIdx.x;

    float* pmS = sm;                 // [64][STR]
    float* gtS = sm + 64 * STR;      // [32][STR]

    const int lane = tid & 31;
    const int w    = tid >> 5;
    const int wd   = w & 1;          // d-half (64 d)
    const int wq   = (w >> 1) & 1;   // q-half (32 q)
    const int wn   = w >> 2;         // n-half 0..1 (16 n)
    const int qtr  = lane & 7;       // q-thread 0..7
    const int ntr  = lane >> 3;      // n-thread 0..3

    unsigned long long acc[4][4];    // 32 registers
    #pragma unroll
    for (int i = 0; i < 4; i++)
        #pragma unroll
        for (int j = 0; j < 4; j++) acc[i][j] = 0ull;

    float rowsum[8];
    #pragma unroll
    for (int i = 0; i < 8; i++) rowsum[i] = 0.f;
    float gsum[4];
    #pragma unroll
    for (int i = 0; i < 4; i++) gsum[i] = 0.f;

    // staging: warp w stages pm rows w+8*it (it 0..7), gt rows w+8*it (it 0..3)
    unsigned vm = 0;
    #pragma unroll
    for (int it = 0; it < 8; it++)
        if (q0 + w + 8 * it < NQ) vm |= 1u << it;

    const size_t pmRow = (size_t)(b * NQ + q0 + w) * DTOT + (size_t)lane * 4;
    const size_t gtRow = (size_t)(b * NGT + w) * DTOT + (size_t)lane * 4;

    const int c0 = (ks * CHTOT) / KS;
    const int c1 = ((ks + 1) * CHTOT) / KS;

    float4 rg[4], rp[8];
    {   // preload chunk c0
        const int kb = c0 * DC;
        #pragma unroll
        for (int it = 0; it < 4; it++)
            rg[it] = *reinterpret_cast<const float4*>(
                gt + gtRow + (size_t)it * 8 * DTOT + kb);
        #pragma unroll
        for (int it = 0; it < 8; it++)
            if ((vm >> it) & 1)
                rp[it] = *reinterpret_cast<const float4*>(
                    pm + pmRow + (size_t)it * 8 * DTOT + kb);
    }

    for (int c = c0; c < c1; c++) {
        // ---- stage current chunk to smem (consumes rp/rg) ----
        #pragma unroll
        for (int it = 0; it < 8; it++) {
            float4 v;
            if ((vm >> it) & 1) {
                v.x = sigf(rp[it].x); v.y = sigf(rp[it].y);
                v.z = sigf(rp[it].z); v.w = sigf(rp[it].w);
                rowsum[it] += (v.x + v.y) + (v.z + v.w);
            } else {
                v = make_float4(0.f, 0.f, 0.f, 0.f);
            }
            *reinterpret_cast<float4*>(&pmS[(w + 8 * it) * STR + lane * 4]) = v;
        }
        #pragma unroll
        for (int it = 0; it < 4; it++) {
            gsum[it] += (rg[it].x + rg[it].y) + (rg[it].z + rg[it].w);
            *reinterpret_cast<float4*>(&gtS[(w + 8 * it) * STR + lane * 4]) = rg[it];
        }
        __syncthreads();

        // ---- prefetch next chunk into registers (flies during compute) ----
        if (c + 1 < c1) {
            const int kb = (c + 1) * DC;
            #pragma unroll
            for (int it = 0; it < 4; it++)
                rg[it] = *reinterpret_cast<const float4*>(
                    gt + gtRow + (size_t)it * 8 * DTOT + kb);
            #pragma unroll
            for (int it = 0; it < 8; it++)
                if ((vm >> it) & 1)
                    rp[it] = *reinterpret_cast<const float4*>(
                        pm + pmRow + (size_t)it * 8 * DTOT + kb);
        }

        // ---- compute: d in [wd*64, wd*64+64), q-half wq, n-half wn ----
        const int db = wd * 64;
        #pragma unroll
        for (int s = 0; s < 16; s++) {
            const int d = db + s * 4;
            ulonglong2 g2[4];
            #pragma unroll
            for (int j = 0; j < 4; j++)
                g2[j] = *reinterpret_cast<const ulonglong2*>(
                    &gtS[(wn * 16 + ntr + 4 * j) * STR + d]);
            #pragma unroll
            for (int i = 0; i < 4; i++) {
                ulonglong2 p2 = *reinterpret_cast<const ulonglong2*>(
                    &pmS[(wq * 32 + qtr + 8 * i) * STR + d]);
                #pragma unroll
                for (int j = 0; j < 4; j++) {
                    ffma2(acc[i][j], p2.x, g2[j].x);
                    ffma2(acc[i][j], p2.y, g2[j].y);
                }
            }
        }
        __syncthreads();
    }

    // ---- deterministic cross-warp reduction via smem ----
    // cell (wd, q, n) unique per (warp,lane,i,j); sum over the 2 d-halves
    float* red = sm;   // [2][2048] floats (4096 <= 64*STR)
    #pragma unroll
    for (int i = 0; i < 4; i++)
        #pragma unroll
        for (int j = 0; j < 4; j++) {
            float2 f2 = *reinterpret_cast<float2*>(&acc[i][j]);
            red[wd * 2048 + (wq * 32 + qtr + 8 * i) * 32 +
                (wn * 16 + ntr + 4 * j)] = f2.x + f2.y;
        }
    __syncthreads();

    for (int o = tid; o < 2048; o += 256) {
        float s = red[o] + red[2048 + o];
        int q = o >> 5;
        if (q0 + q < NQ)
            g_part[((size_t)(ks * 4 + b) * NQ + q0 + q) * 32 + (o & 31)] = s;
    }

    // ---- per-q sigmoid sums (q = w + 8*it is warp-uniform) ----
    #pragma unroll
    for (int it = 0; it < 8; it++) {
        float s = rowsum[it];
        #pragma unroll
        for (int off = 16; off; off >>= 1)
            s += __shfl_down_sync(0xffffffffu, s, off);
        if (lane == 0 && ((vm >> it) & 1))
            g_psum[(ks * 4 + b) * NQ + q0 + w + 8 * it] = s;
    }
    // ---- per-n gt sums (qt==0 blocks only; n = w + 8*it warp-uniform) ----
    if (qt == 0) {
        #pragma unroll
        for (int it = 0; it < 4; it++) {
            float s = gsum[it];
            #pragma unroll
            for (int off = 16; off; off >>= 1)
                s += __shfl_down_sync(0xffffffffu, s, off);
            if (lane == 0)
                g_gtp[(ks * 4 + b) * NGT + w + 8 * it] = s;
        }
    }
}

// ---------------------------------------------------------------------------
// Kernel R: reduce partials -> combined scores. grid(4, 25), 256 thr.
// One output element per thread; 18 independent loads -> latency-tolerant.
// ---------------------------------------------------------------------------
__global__ void __launch_bounds__(256)
kR(const float* __restrict__ logits) {
    const int b = blockIdx.x, yo = blockIdx.y, tid = threadIdx.x;
    __shared__ float psS[8], clsS[8], gsS[32];

    if (tid < 8) {
        int q = yo * 8 + tid;
        float s = 0.f;
        #pragma unroll
        for (int z = 0; z < KS; z++) s += g_psum[(z * 4 + b) * NQ + q];
        psS[tid] = s;
        float l0 = logits[(b * NQ + q) * 2 + 0];
        float l1 = logits[(b * NQ + q) * 2 + 1];
        clsS[tid] = 1.0f / (1.0f + expf(l0 - l1));   // softmax(...)[1]
    } else if (tid >= 32 && tid < 64) {
        int n = tid - 32;
        float s = 0.f;
        #pragma unroll
        for (int z = 0; z < KS; z++) s += g_gtp[(z * 4 + b) * NGT + n];
        gsS[n] = s;
    }
    __syncthreads();

    const int o = yo * 256 + tid;            // 0..6399
    const int q = o >> 5, n = o & 31;
    float inter = 0.f;
    #pragma unroll
    for (int z = 0; z < KS; z++)
        inter += g_part[((size_t)(z * 4 + b) * NQ + q) * 32 + n];
    g_comb[b * NQ * NGT + o] =
        inter / (psS[tid >> 5] + gsS[n] - inter + 1e-6f) * clsS[tid >> 5];
}

// ---------------------------------------------------------------------------
// Kernel C2: per-column top-4 + parallel dedup + output. grid(4), 256 thr.
// OUTPUT is float32: src||tgt||valid as floats (512 each).
// ---------------------------------------------------------------------------
__global__ void __launch_bounds__(256)
kC2(float* __restrict__ out) {
    const int b = blockIdx.x, tid = threadIdx.x;
    __shared__ float comb[NQ * NGT];
    __shared__ int top4[NGT * 4];

    for (int o = tid; o < NQ * NGT; o += 256)
        comb[o] = g_comb[b * NQ * NGT + o];
    __syncthreads();

    // per-column top-4 (warp w handles columns 4w..4w+3); tie -> lower q
    const int w = tid >> 5, lane = tid & 31;
    for (int n = w * 4; n < w * 4 + 4; n++) {
        float v[7];
        #pragma unroll
        for (int t = 0; t < 7; t++) {
            int q = lane + 32 * t;
            v[t] = (q < NQ) ? comb[q * 32 + n] : -1e30f;
        }
        unsigned selmask = 0;
        for (int kk = 0; kk < 4; kk++) {
            float bv = -1e30f; int bq = 1 << 20;
            #pragma unroll
            for (int t = 0; t < 7; t++) {
                int q = lane + 32 * t;
                if (!((selmask >> t) & 1) && q < NQ) {
                    if (v[t] > bv || (v[t] == bv && q < bq)) { bv = v[t]; bq = q; }
                }
            }
            for (int off = 16; off; off >>= 1) {
                float ov = __shfl_xor_sync(0xffffffffu, bv, off);
                int   oq = __shfl_xor_sync(0xffffffffu, bq, off);
                if (ov > bv || (ov == bv && oq < bq)) { bv = ov; bq = oq; }
            }
            if (lane == 0) top4[n * 4 + kk] = bq;
            if ((bq & 31) == lane) selmask |= 1u << (bq >> 5);
        }
    }
    __syncthreads();

    // parallel dedup: slot (n,kk) dropped iff its q appears in an earlier
    // column's top-4 (within-column indices are distinct -> matches greedy scan)
    if (tid < NGT * 4) {
        int q = top4[tid];
        int n = tid >> 2;
        bool dup = false;
        for (int sp = 0; sp < (n << 2); sp++) dup |= (top4[sp] == q);
        int sel = dup ? -1 : q;
        int o = (b * NGT + n) * 4 + (tid & 3);
        out[o]        = (float)sel;                    // src_idx
        out[512 + o]  = (sel >= 0) ? (float)n : -1.0f; // tgt_idx
        out[1024 + o] = (sel >= 0) ? 1.0f : 0.0f;      // valid
    }
}

extern "C" void kernel_launch(void* const* d_in, const int* in_sizes, int n_in,
                              void* d_out, int out_size) {
    const float* pm = (const float*)d_in[0];   // [4,200,256,256]
    const float* lg = (const float*)d_in[1];   // [4,200,2]
    const float* gt = (const float*)d_in[2];   // [4,32,256,256]
    float* out = (float*)d_out;

    const int smemA = (96 * STR) * sizeof(float);  // 50688 B
    cudaFuncSetAttribute(kA, cudaFuncAttributeMaxDynamicSharedMemorySize, smemA);

    kA<<<dim3(KS, 4, 4), 256, smemA>>>(pm, gt);
    kR<<<dim3(4, 25), 256>>>(lg);
    kC2<<<4, 256>>>(out);
}

// round 15
// speedup vs baseline: 1.1701x; 1.1701x over previous
#include <cuda_runtime.h>
#include <cuda_bf16.h>
#include <math.h>

#define KS   18           // k-splits: grid 288 = 2 CTAs/SM
#define DCH  128          // d per chunk
#define NCH  512          // 65536 / 128
#define NQ   200
#define NGT  32
#define DTOT 65536
#define BSTR 68           // B smem row stride in uints (272 B): 64 data + 4 pad

// ---- scratch (static __device__, per allocation rules) ----
__device__ float g_part[KS * 4 * NQ * NGT];
__device__ float g_psum[KS * 4 * NQ];
__device__ float g_gtp[KS * 4 * NGT];
__device__ float g_comb[4 * NQ * NGT];

__device__ __forceinline__ float sigf(float x) {
    return __fdividef(1.0f, 1.0f + __expf(-x));
}
// pack (a,b) -> bf16x2 hi + bf16x2 lo (exact split: a = hi + lo to ~2^-18 rel)
__device__ __forceinline__ void split_bf16(float a, float b,
                                           unsigned& hi, unsigned& lo) {
    __nv_bfloat162 h = __floats2bfloat162_rn(a, b);
    hi = *reinterpret_cast<unsigned*>(&h);
    __nv_bfloat162 l = __floats2bfloat162_rn(a - __bfloat162float(h.x),
                                             b - __bfloat162float(h.y));
    lo = *reinterpret_cast<unsigned*>(&l);
}
__device__ __forceinline__ void mma16816(float* c, const unsigned* a,
                                         unsigned b0, unsigned b1) {
    asm volatile(
        "mma.sync.aligned.m16n8k16.row.col.f32.bf16.bf16.f32 "
        "{%0,%1,%2,%3}, {%4,%5,%6,%7}, {%8,%9}, {%0,%1,%2,%3};"
        : "+f"(c[0]), "+f"(c[1]), "+f"(c[2]), "+f"(c[3])
        : "r"(a[0]), "r"(a[1]), "r"(a[2]), "r"(a[3]), "r"(b0), "r"(b1));
}

// ---------------------------------------------------------------------------
// Kernel T: sigmoid + hi/lo bf16 split -> mma.sync GEMM, K-split.
// grid(KS, 4 qtiles of 64, 4 batches), 256 thr, 2 CTAs/SM.
// Warp w: wq = w&3 (16-q tile), wd = w>>2 (64-d half of the 128-d chunk).
// A fragments built directly in registers from global pm (sigmoid fused);
// B (gt, exact in bf16) staged in smem, 272B row stride (conflict-free reads).
// ---------------------------------------------------------------------------
__global__ void __launch_bounds__(256, 2)
kT(const float* __restrict__ pm, const float* __restrict__ gt) {
    __shared__ float    redS[4096];            // 16 KB cross-wd reduction
    __shared__ unsigned bS[32 * BSTR];         // B tile: 32 rows x 272 B (bf16)
    __shared__ float    psumS[128];            // [2][64] per-q sigmoid partials

    const int ks = blockIdx.x, qt = blockIdx.y, b = blockIdx.z;
    const int q0 = qt * 64;
    const int tid = threadIdx.x, lane = tid & 31, w = tid >> 5;
    const int wq = w & 3, wd = w >> 2;
    const int gr = lane >> 2, th4 = lane & 3;

    float acc[4][4];
    #pragma unroll
    for (int j = 0; j < 4; j++)
        #pragma unroll
        for (int i = 0; i < 4; i++) acc[j][i] = 0.f;

    float rs0 = 0.f, rs1 = 0.f, gsum = 0.f;

    // B staging map: thread t -> gt row bn = t>>3, 16-d segment bseg = t&7
    const int bn = tid >> 3, bseg = tid & 7;
    const float* gtp = gt + (size_t)(b * NGT + bn) * DTOT + bseg * 16;

    // A fragment map: rows qA0 = q0 + wq*16 + gr, qA1 = qA0 + 8
    const int qA0 = q0 + wq * 16 + gr, qA1 = qA0 + 8;
    const bool v0 = qA0 < NQ, v1 = qA1 < NQ;
    const float* pA0 = pm + (size_t)(b * NQ + (v0 ? qA0 : 0)) * DTOT + wd * 64 + th4 * 2;
    const float* pA1 = pm + (size_t)(b * NQ + (v1 ? qA1 : 0)) * DTOT + wd * 64 + th4 * 2;

    const int c0 = (ks * NCH) / KS, c1 = ((ks + 1) * NCH) / KS;

    float2 rA0[4], rA1[4], rA0b[4], rA1b[4];   // kstep s: (qA0,k),(qA1,k),(qA0,k+8),(qA1,k+8)
    float4 rB[4];

    {   // preload chunk c0
        const int kb = c0 * DCH;
        #pragma unroll
        for (int s = 0; s < 4; s++) {
            if (v0) {
                rA0[s]  = *reinterpret_cast<const float2*>(pA0 + kb + s * 16);
                rA0b[s] = *reinterpret_cast<const float2*>(pA0 + kb + s * 16 + 8);
            }
            if (v1) {
                rA1[s]  = *reinterpret_cast<const float2*>(pA1 + kb + s * 16);
                rA1b[s] = *reinterpret_cast<const float2*>(pA1 + kb + s * 16 + 8);
            }
        }
        #pragma unroll
        for (int i = 0; i < 4; i++)
            rB[i] = *reinterpret_cast<const float4*>(gtp + kb + i * 4);
    }

    for (int c = c0; c < c1; c++) {
        // ---- stage B chunk (gt exact in bf16); accumulate gt row sums ----
        #pragma unroll
        for (int i = 0; i < 4; i++) {
            float4 v = rB[i];
            gsum += (v.x + v.y) + (v.z + v.w);
            __nv_bfloat162 p0 = __floats2bfloat162_rn(v.x, v.y);
            __nv_bfloat162 p1 = __floats2bfloat162_rn(v.z, v.w);
            *reinterpret_cast<uint2*>(
                reinterpret_cast<char*>(bS) + bn * (BSTR * 4) + bseg * 32 + i * 8) =
                make_uint2(*reinterpret_cast<unsigned*>(&p0),
                           *reinterpret_cast<unsigned*>(&p1));
        }

        // ---- build A fragments: sigmoid + hi/lo split (frees rA regs) ----
        unsigned ah[4][4], al[4][4];
        #pragma unroll
        for (int s = 0; s < 4; s++) {
            float x0 = 0.f, x1 = 0.f;
            if (v0) { x0 = sigf(rA0[s].x);  x1 = sigf(rA0[s].y);  rs0 += x0 + x1; }
            split_bf16(x0, x1, ah[s][0], al[s][0]);
            x0 = x1 = 0.f;
            if (v1) { x0 = sigf(rA1[s].x);  x1 = sigf(rA1[s].y);  rs1 += x0 + x1; }
            split_bf16(x0, x1, ah[s][1], al[s][1]);
            x0 = x1 = 0.f;
            if (v0) { x0 = sigf(rA0b[s].x); x1 = sigf(rA0b[s].y); rs0 += x0 + x1; }
            split_bf16(x0, x1, ah[s][2], al[s][2]);
            x0 = x1 = 0.f;
            if (v1) { x0 = sigf(rA1b[s].x); x1 = sigf(rA1b[s].y); rs1 += x0 + x1; }
            split_bf16(x0, x1, ah[s][3], al[s][3]);
        }
        __syncthreads();   // B tile visible

        // ---- prefetch next chunk (in flight during MMA phase) ----
        if (c + 1 < c1) {
            const int kb = (c + 1) * DCH;
            #pragma unroll
            for (int s = 0; s < 4; s++) {
                if (v0) {
                    rA0[s]  = *reinterpret_cast<const float2*>(pA0 + kb + s * 16);
                    rA0b[s] = *reinterpret_cast<const float2*>(pA0 + kb + s * 16 + 8);
                }
                if (v1) {
                    rA1[s]  = *reinterpret_cast<const float2*>(pA1 + kb + s * 16);
                    rA1b[s] = *reinterpret_cast<const float2*>(pA1 + kb + s * 16 + 8);
                }
            }
            #pragma unroll
            for (int i = 0; i < 4; i++)
                rB[i] = *reinterpret_cast<const float4*>(gtp + kb + i * 4);
        }

        // ---- MMA: 4 ksteps x 4 ntiles x {hi, lo} ----
        #pragma unroll
        for (int s = 0; s < 4; s++) {
            const int kw = (wd * 64 + s * 16) / 2 + th4;  // uint index in B row
            #pragma unroll
            for (int j = 0; j < 4; j++) {
                unsigned b0 = bS[(j * 8 + gr) * BSTR + kw];
                unsigned b1 = bS[(j * 8 + gr) * BSTR + kw + 4];
                mma16816(acc[j], ah[s], b0, b1);
                mma16816(acc[j], al[s], b0, b1);
            }
        }
        __syncthreads();   // done reading B before next restage
    }

    // ---- cross-wd reduction (deterministic) ----
    #pragma unroll
    for (int j = 0; j < 4; j++) {
        const int n = j * 8 + th4 * 2;
        redS[wd * 2048 + (wq * 16 + gr) * 32 + n]         = acc[j][0];
        redS[wd * 2048 + (wq * 16 + gr) * 32 + n + 1]     = acc[j][1];
        redS[wd * 2048 + (wq * 16 + gr + 8) * 32 + n]     = acc[j][2];
        redS[wd * 2048 + (wq * 16 + gr + 8) * 32 + n + 1] = acc[j][3];
    }
    // per-q sigmoid sums: reduce over the 4 lanes sharing a q row
    rs0 += __shfl_down_sync(0xffffffffu, rs0, 2);
    rs0 += __shfl_down_sync(0xffffffffu, rs0, 1);
    rs1 += __shfl_down_sync(0xffffffffu, rs1, 2);
    rs1 += __shfl_down_sync(0xffffffffu, rs1, 1);
    if (th4 == 0) {
        psumS[wd * 64 + wq * 16 + gr]     = rs0;
        psumS[wd * 64 + wq * 16 + gr + 8] = rs1;
    }
    __syncthreads();

    for (int o = tid; o < 2048; o += 256) {
        float s = redS[o] + redS[2048 + o];
        int q = o >> 5;
        if (q0 + q < NQ)
            g_part[((size_t)(ks * 4 + b) * NQ + q0 + q) * 32 + (o & 31)] = s;
    }
    if (tid < 64 && q0 + tid < NQ)
        g_psum[(ks * 4 + b) * NQ + q0 + tid] = psumS[tid] + psumS[64 + tid];

    // per-n gt sums (qt==0 only): 8 consecutive threads share row n
    if (qt == 0) {
        gsum += __shfl_down_sync(0xffffffffu, gsum, 4);
        gsum += __shfl_down_sync(0xffffffffu, gsum, 2);
        gsum += __shfl_down_sync(0xffffffffu, gsum, 1);
        if ((tid & 7) == 0)
            g_gtp[(ks * 4 + b) * NGT + (tid >> 3)] = gsum;
    }
}

// ---------------------------------------------------------------------------
// Kernel R: reduce partials -> combined scores. grid(4, 25), 256 thr.
// ---------------------------------------------------------------------------
__global__ void __launch_bounds__(256)
kR(const float* __restrict__ logits) {
    const int b = blockIdx.x, yo = blockIdx.y, tid = threadIdx.x;
    __shared__ float psS[8], clsS[8], gsS[32];

    if (tid < 8) {
        int q = yo * 8 + tid;
        float s = 0.f;
        #pragma unroll
        for (int z = 0; z < KS; z++) s += g_psum[(z * 4 + b) * NQ + q];
        psS[tid] = s;
        float l0 = logits[(b * NQ + q) * 2 + 0];
        float l1 = logits[(b * NQ + q) * 2 + 1];
        clsS[tid] = 1.0f / (1.0f + expf(l0 - l1));   // softmax(...)[1]
    } else if (tid >= 32 && tid < 64) {
        int n = tid - 32;
        float s = 0.f;
        #pragma unroll
        for (int z = 0; z < KS; z++) s += g_gtp[(z * 4 + b) * NGT + n];
        gsS[n] = s;
    }
    __syncthreads();

    const int o = yo * 256 + tid;
    const int q = o >> 5, n = o & 31;
    float inter = 0.f;
    #pragma unroll
    for (int z = 0; z < KS; z++)
        inter += g_part[((size_t)(z * 4 + b) * NQ + q) * 32 + n];
    g_comb[b * NQ * NGT + o] =
        inter / (psS[tid >> 5] + gsS[n] - inter + 1e-6f) * clsS[tid >> 5];
}

// ---------------------------------------------------------------------------
// Kernel C2: per-column top-4 + parallel dedup + output. grid(4), 256 thr.
// OUTPUT is float32: src||tgt||valid as floats (512 each).
// ---------------------------------------------------------------------------
__global__ void __launch_bounds__(256)
kC2(float* __restrict__ out) {
    const int b = blockIdx.x, tid = threadIdx.x;
    __shared__ float comb[NQ * NGT];
    __shared__ int top4[NGT * 4];

    for (int o = tid; o < NQ * NGT; o += 256)
        comb[o] = g_comb[b * NQ * NGT + o];
    __syncthreads();

    const int w = tid >> 5, lane = tid & 31;
    for (int n = w * 4; n < w * 4 + 4; n++) {
        float v[7];
        #pragma unroll
        for (int t = 0; t < 7; t++) {
            int q = lane + 32 * t;
            v[t] = (q < NQ) ? comb[q * 32 + n] : -1e30f;
        }
        unsigned selmask = 0;
        for (int kk = 0; kk < 4; kk++) {
            float bv = -1e30f; int bq = 1 << 20;
            #pragma unroll
            for (int t = 0; t < 7; t++) {
                int q = lane + 32 * t;
                if (!((selmask >> t) & 1) && q < NQ) {
                    if (v[t] > bv || (v[t] == bv && q < bq)) { bv = v[t]; bq = q; }
                }
            }
            for (int off = 16; off; off >>= 1) {
                float ov = __shfl_xor_sync(0xffffffffu, bv, off);
                int   oq = __shfl_xor_sync(0xffffffffu, bq, off);
                if (ov > bv || (ov == bv && oq < bq)) { bv = ov; bq = oq; }
            }
            if (lane == 0) top4[n * 4 + kk] = bq;
            if ((bq & 31) == lane) selmask |= 1u << (bq >> 5);
        }
    }
    __syncthreads();

    if (tid < NGT * 4) {
        int q = top4[tid];
        int n = tid >> 2;
        bool dup = false;
        for (int sp = 0; sp < (n << 2); sp++) dup |= (top4[sp] == q);
        int sel = dup ? -1 : q;
        int o = (b * NGT + n) * 4 + (tid & 3);
        out[o]        = (float)sel;
        out[512 + o]  = (sel >= 0) ? (float)n : -1.0f;
        out[1024 + o] = (sel >= 0) ? 1.0f : 0.0f;
    }
}

extern "C" void kernel_launch(void* const* d_in, const int* in_sizes, int n_in,
                              void* d_out, int out_size) {
    const float* pm = (const float*)d_in[0];   // [4,200,256,256]
    const float* lg = (const float*)d_in[1];   // [4,200,2]
    const float* gt = (const float*)d_in[2];   // [4,32,256,256]
    float* out = (float*)d_out;

    kT<<<dim3(KS, 4, 4), 256>>>(pm, gt);
    kR<<<dim3(4, 25), 256>>>(lg);
    kC2<<<4, 256>>>(out);
}

// round 16
// speedup vs baseline: 1.9917x; 1.7021x over previous
#include <cuda_runtime.h>
#include <cuda_bf16.h>
#include <math.h>

#define KS   18           // k-splits: grid 288 = 2 CTAs/SM
#define DCH  128          // d per chunk
#define NCH  512          // 65536 / 128
#define NQ   200
#define NGT  32
#define DTOT 65536
#define BSTR 68           // B smem row stride in uints (272 B): 64 data + 4 pad

// ---- scratch (static __device__, per allocation rules) ----
__device__ float g_part[KS * 4 * NQ * NGT];
__device__ float g_psum[KS * 4 * NQ];
__device__ float g_gtp[KS * 4 * NGT];
__device__ float g_comb[4 * NQ * NGT];

__device__ __forceinline__ float sigf(float x) {
    return __fdividef(1.0f, 1.0f + __expf(-x));
}
// pack (a,b) -> bf16x2 hi + bf16x2 lo (split: a = hi + lo to ~2^-18 rel)
__device__ __forceinline__ void split_bf16(float a, float b,
                                           unsigned& hi, unsigned& lo) {
    __nv_bfloat162 h = __floats2bfloat162_rn(a, b);
    hi = *reinterpret_cast<unsigned*>(&h);
    __nv_bfloat162 l = __floats2bfloat162_rn(a - __bfloat162float(h.x),
                                             b - __bfloat162float(h.y));
    lo = *reinterpret_cast<unsigned*>(&l);
}
__device__ __forceinline__ void mma16816(float* c, const unsigned* a,
                                         unsigned b0, unsigned b1) {
    asm volatile(
        "mma.sync.aligned.m16n8k16.row.col.f32.bf16.bf16.f32 "
        "{%0,%1,%2,%3}, {%4,%5,%6,%7}, {%8,%9}, {%0,%1,%2,%3};"
        : "+f"(c[0]), "+f"(c[1]), "+f"(c[2]), "+f"(c[3])
        : "r"(a[0]), "r"(a[1]), "r"(a[2]), "r"(a[3]), "r"(b0), "r"(b1));
}

// ---------------------------------------------------------------------------
// Kernel T: sigmoid + hi/lo bf16 split -> mma.sync GEMM, K-split.
// grid(KS, 4 qtiles of 64, 4 batches), 256 thr, 2 CTAs/SM.
// Warp w: wq = w&3 (16-q tile), wd = w>>2 (64-d half of the 128-d chunk).
// A fragments in registers (sigmoid fused); B double-buffered in smem with
// ONE barrier per chunk -> convert(c+1) overlaps other warps' MMA(c).
// ---------------------------------------------------------------------------
__global__ void __launch_bounds__(256, 2)
kT(const float* __restrict__ pm, const float* __restrict__ gt) {
    __shared__ float    redS[4096];            // 16 KB cross-wd reduction
    __shared__ unsigned bS[2][32 * BSTR];      // B tiles, double buffered
    __shared__ float    psumS[128];            // [2][64] per-q sigmoid partials

    const int ks = blockIdx.x, qt = blockIdx.y, b = blockIdx.z;
    const int q0 = qt * 64;
    const int tid = threadIdx.x, lane = tid & 31, w = tid >> 5;
    const int wq = w & 3, wd = w >> 2;
    const int gr = lane >> 2, th4 = lane & 3;

    float acc[4][4];
    #pragma unroll
    for (int j = 0; j < 4; j++)
        #pragma unroll
        for (int i = 0; i < 4; i++) acc[j][i] = 0.f;

    float rs0 = 0.f, rs1 = 0.f, gsum = 0.f;

    // B staging map: thread t -> gt row bn = t>>3, 16-d segment bseg = t&7
    const int bn = tid >> 3, bseg = tid & 7;
    const float* gtp = gt + (size_t)(b * NGT + bn) * DTOT + bseg * 16;

    // A fragment map: rows qA0 = q0 + wq*16 + gr, qA1 = qA0 + 8
    const int qA0 = q0 + wq * 16 + gr, qA1 = qA0 + 8;
    const bool v0 = qA0 < NQ, v1 = qA1 < NQ;
    const float* pA0 = pm + (size_t)(b * NQ + (v0 ? qA0 : 0)) * DTOT + wd * 64 + th4 * 2;
    const float* pA1 = pm + (size_t)(b * NQ + (v1 ? qA1 : 0)) * DTOT + wd * 64 + th4 * 2;

    const int c0 = (ks * NCH) / KS, c1 = ((ks + 1) * NCH) / KS;

    float2 rA0[4], rA1[4], rA0b[4], rA1b[4];   // kstep s: (qA0,k),(qA1,k),(qA0,k+8),(qA1,k+8)
    float4 rB[4];

    {   // preload chunk c0
        const int kb = c0 * DCH;
        #pragma unroll
        for (int s = 0; s < 4; s++) {
            if (v0) {
                rA0[s]  = *reinterpret_cast<const float2*>(pA0 + kb + s * 16);
                rA0b[s] = *reinterpret_cast<const float2*>(pA0 + kb + s * 16 + 8);
            }
            if (v1) {
                rA1[s]  = *reinterpret_cast<const float2*>(pA1 + kb + s * 16);
                rA1b[s] = *reinterpret_cast<const float2*>(pA1 + kb + s * 16 + 8);
            }
        }
        #pragma unroll
        for (int i = 0; i < 4; i++)
            rB[i] = *reinterpret_cast<const float4*>(gtp + kb + i * 4);
    }

    for (int c = c0; c < c1; c++) {
        const int buf = c & 1;

        // ---- stage B chunk (consumes rB); accumulate gt row sums ----
        #pragma unroll
        for (int i = 0; i < 4; i++) {
            float4 v = rB[i];
            gsum += (v.x + v.y) + (v.z + v.w);
            __nv_bfloat162 p0 = __floats2bfloat162_rn(v.x, v.y);
            __nv_bfloat162 p1 = __floats2bfloat162_rn(v.z, v.w);
            *reinterpret_cast<uint2*>(
                reinterpret_cast<char*>(bS[buf]) + bn * (BSTR * 4) + bseg * 32 + i * 8) =
                make_uint2(*reinterpret_cast<unsigned*>(&p0),
                           *reinterpret_cast<unsigned*>(&p1));
        }
        // ---- prefetch next B immediately (widest latency window) ----
        if (c + 1 < c1) {
            const int kb = (c + 1) * DCH;
            #pragma unroll
            for (int i = 0; i < 4; i++)
                rB[i] = *reinterpret_cast<const float4*>(gtp + kb + i * 4);
        }

        // ---- build A fragments: sigmoid + hi/lo split (consumes rA) ----
        unsigned ah[4][4], al[4][4];
        #pragma unroll
        for (int s = 0; s < 4; s++) {
            float x0 = 0.f, x1 = 0.f;
            if (v0) { x0 = sigf(rA0[s].x);  x1 = sigf(rA0[s].y);  rs0 += x0 + x1; }
            split_bf16(x0, x1, ah[s][0], al[s][0]);
            x0 = x1 = 0.f;
            if (v1) { x0 = sigf(rA1[s].x);  x1 = sigf(rA1[s].y);  rs1 += x0 + x1; }
            split_bf16(x0, x1, ah[s][1], al[s][1]);
            x0 = x1 = 0.f;
            if (v0) { x0 = sigf(rA0b[s].x); x1 = sigf(rA0b[s].y); rs0 += x0 + x1; }
            split_bf16(x0, x1, ah[s][2], al[s][2]);
            x0 = x1 = 0.f;
            if (v1) { x0 = sigf(rA1b[s].x); x1 = sigf(rA1b[s].y); rs1 += x0 + x1; }
            split_bf16(x0, x1, ah[s][3], al[s][3]);
        }
        // ---- prefetch next A (in flight through sync + MMA) ----
        if (c + 1 < c1) {
            const int kb = (c + 1) * DCH;
            #pragma unroll
            for (int s = 0; s < 4; s++) {
                if (v0) {
                    rA0[s]  = *reinterpret_cast<const float2*>(pA0 + kb + s * 16);
                    rA0b[s] = *reinterpret_cast<const float2*>(pA0 + kb + s * 16 + 8);
                }
                if (v1) {
                    rA1[s]  = *reinterpret_cast<const float2*>(pA1 + kb + s * 16);
                    rA1b[s] = *reinterpret_cast<const float2*>(pA1 + kb + s * 16 + 8);
                }
            }
        }

        // ---- ONE barrier: bS[buf] published; prior MMA readers all done ----
        __syncthreads();

        // ---- MMA: 4 ksteps x 4 ntiles x {hi, lo} ----
        #pragma unroll
        for (int s = 0; s < 4; s++) {
            const int kw = (wd * 64 + s * 16) / 2 + th4;  // uint index in B row
            #pragma unroll
            for (int j = 0; j < 4; j++) {
                unsigned b0 = bS[buf][(j * 8 + gr) * BSTR + kw];
                unsigned b1 = bS[buf][(j * 8 + gr) * BSTR + kw + 4];
                mma16816(acc[j], ah[s], b0, b1);
                mma16816(acc[j], al[s], b0, b1);
            }
        }
        // no second barrier: next stage writes bS[buf^1], safe by induction
    }
    __syncthreads();

    // ---- cross-wd reduction (deterministic) ----
    #pragma unroll
    for (int j = 0; j < 4; j++) {
        const int n = j * 8 + th4 * 2;
        redS[wd * 2048 + (wq * 16 + gr) * 32 + n]         = acc[j][0];
        redS[wd * 2048 + (wq * 16 + gr) * 32 + n + 1]     = acc[j][1];
        redS[wd * 2048 + (wq * 16 + gr + 8) * 32 + n]     = acc[j][2];
        redS[wd * 2048 + (wq * 16 + gr + 8) * 32 + n + 1] = acc[j][3];
    }
    // per-q sigmoid sums: reduce over the 4 lanes sharing a q row
    rs0 += __shfl_down_sync(0xffffffffu, rs0, 2);
    rs0 += __shfl_down_sync(0xffffffffu, rs0, 1);
    rs1 += __shfl_down_sync(0xffffffffu, rs1, 2);
    rs1 += __shfl_down_sync(0xffffffffu, rs1, 1);
    if (th4 == 0) {
        psumS[wd * 64 + wq * 16 + gr]     = rs0;
        psumS[wd * 64 + wq * 16 + gr + 8] = rs1;
    }
    __syncthreads();

    for (int o = tid; o < 2048; o += 256) {
        float s = redS[o] + redS[2048 + o];
        int q = o >> 5;
        if (q0 + q < NQ)
            g_part[((size_t)(ks * 4 + b) * NQ + q0 + q) * 32 + (o & 31)] = s;
    }
    if (tid < 64 && q0 + tid < NQ)
        g_psum[(ks * 4 + b) * NQ + q0 + tid] = psumS[tid] + psumS[64 + tid];

    // per-n gt sums (qt==0 only): 8 consecutive threads share row n
    if (qt == 0) {
        gsum += __shfl_down_sync(0xffffffffu, gsum, 4);
        gsum += __shfl_down_sync(0xffffffffu, gsum, 2);
        gsum += __shfl_down_sync(0xffffffffu, gsum, 1);
        if ((tid & 7) == 0)
            g_gtp[(ks * 4 + b) * NGT + (tid >> 3)] = gsum;
    }
}

// ---------------------------------------------------------------------------
// Kernel R: reduce partials -> combined scores. grid(4, 25), 256 thr.
// ---------------------------------------------------------------------------
__global__ void __launch_bounds__(256)
kR(const float* __restrict__ logits) {
    const int b = blockIdx.x, yo = blockIdx.y, tid = threadIdx.x;
    __shared__ float psS[8], clsS[8], gsS[32];

    if (tid < 8) {
        int q = yo * 8 + tid;
        float s = 0.f;
        #pragma unroll
        for (int z = 0; z < KS; z++) s += g_psum[(z * 4 + b) * NQ + q];
        psS[tid] = s;
        float l0 = logits[(b * NQ + q) * 2 + 0];
        float l1 = logits[(b * NQ + q) * 2 + 1];
        clsS[tid] = 1.0f / (1.0f + expf(l0 - l1));   // softmax(...)[1]
    } else if (tid >= 32 && tid < 64) {
        int n = tid - 32;
        float s = 0.f;
        #pragma unroll
        for (int z = 0; z < KS; z++) s += g_gtp[(z * 4 + b) * NGT + n];
        gsS[n] = s;
    }
    __syncthreads();

    const int o = yo * 256 + tid;
    const int q = o >> 5, n = o & 31;
    float inter = 0.f;
    #pragma unroll
    for (int z = 0; z < KS; z++)
        inter += g_part[((size_t)(z * 4 + b) * NQ + q) * 32 + n];
    g_comb[b * NQ * NGT + o] =
        inter / (psS[tid >> 5] + gsS[n] - inter + 1e-6f) * clsS[tid >> 5];
}

// ---------------------------------------------------------------------------
// Kernel C2: per-column top-4 + parallel dedup + output. grid(4), 256 thr.
// OUTPUT is float32: src||tgt||valid as floats (512 each).
// ---------------------------------------------------------------------------
__global__ void __launch_bounds__(256)
kC2(float* __restrict__ out) {
    const int b = blockIdx.x, tid = threadIdx.x;
    __shared__ float comb[NQ * NGT];
    __shared__ int top4[NGT * 4];

    for (int o = tid; o < NQ * NGT; o += 256)
        comb[o] = g_comb[b * NQ * NGT + o];
    __syncthreads();

    const int w = tid >> 5, lane = tid & 31;
    for (int n = w * 4; n < w * 4 + 4; n++) {
        float v[7];
        #pragma unroll
        for (int t = 0; t < 7; t++) {
            int q = lane + 32 * t;
            v[t] = (q < NQ) ? comb[q * 32 + n] : -1e30f;
        }
        unsigned selmask = 0;
        for (int kk = 0; kk < 4; kk++) {
            float bv = -1e30f; int bq = 1 << 20;
            #pragma unroll
            for (int t = 0; t < 7; t++) {
                int q = lane + 32 * t;
                if (!((selmask >> t) & 1) && q < NQ) {
                    if (v[t] > bv || (v[t] == bv && q < bq)) { bv = v[t]; bq = q; }
                }
            }
            for (int off = 16; off; off >>= 1) {
                float ov = __shfl_xor_sync(0xffffffffu, bv, off);
                int   oq = __shfl_xor_sync(0xffffffffu, bq, off);
                if (ov > bv || (ov == bv && oq < bq)) { bv = ov; bq = oq; }
            }
            if (lane == 0) top4[n * 4 + kk] = bq;
            if ((bq & 31) == lane) selmask |= 1u << (bq >> 5);
        }
    }
    __syncthreads();

    if (tid < NGT * 4) {
        int q = top4[tid];
        int n = tid >> 2;
        bool dup = false;
        for (int sp = 0; sp < (n << 2); sp++) dup |= (top4[sp] == q);
        int sel = dup ? -1 : q;
        int o = (b * NGT + n) * 4 + (tid & 3);
        out[o]        = (float)sel;
        out[512 + o]  = (sel >= 0) ? (float)n : -1.0f;
        out[1024 + o] = (sel >= 0) ? 1.0f : 0.0f;
    }
}

extern "C" void kernel_launch(void* const* d_in, const int* in_sizes, int n_in,
                              void* d_out, int out_size) {
    const float* pm = (const float*)d_in[0];   // [4,200,256,256]
    const float* lg = (const float*)d_in[1];   // [4,200,2]
    const float* gt = (const float*)d_in[2];   // [4,32,256,256]
    float* out = (float*)d_out;

    kT<<<dim3(KS, 4, 4), 256>>>(pm, gt);
    kR<<<dim3(4, 25), 256>>>(lg);
    kC2<<<4, 256>>>(out);
}

// round 17
// speedup vs baseline: 2.1917x; 1.1004x over previous
#include <cuda_runtime.h>
#include <cuda_bf16.h>
#include <math.h>

#define KS   28           // k-splits: grid 448 ~= 3 CTAs/SM
#define DCH  64           // d per chunk
#define NCH  1024         // 65536 / 64
#define NQ   200
#define NGT  32
#define DTOT 65536
#define BROW 144          // B smem row stride in bytes: 128 data + 16 pad

// ---- scratch (static __device__, per allocation rules) ----
__device__ float g_part[KS * 4 * NQ * NGT];
__device__ float g_psum[KS * 4 * NQ];
__device__ float g_gtp[KS * 4 * NGT];
__device__ float g_comb[4 * NQ * NGT];

__device__ __forceinline__ float sigf(float x) {
    return __fdividef(1.0f, 1.0f + __expf(-x));
}
// pack (a,b) -> bf16x2 hi + bf16x2 lo (split: a = hi + lo to ~2^-17 rel)
__device__ __forceinline__ void split_bf16(float a, float b,
                                           unsigned& hi, unsigned& lo) {
    __nv_bfloat162 h = __floats2bfloat162_rn(a, b);
    hi = *reinterpret_cast<unsigned*>(&h);
    __nv_bfloat162 l = __floats2bfloat162_rn(a - __bfloat162float(h.x),
                                             b - __bfloat162float(h.y));
    lo = *reinterpret_cast<unsigned*>(&l);
}
__device__ __forceinline__ void mma16816(float* c, const unsigned* a,
                                         unsigned b0, unsigned b1) {
    asm volatile(
        "mma.sync.aligned.m16n8k16.row.col.f32.bf16.bf16.f32 "
        "{%0,%1,%2,%3}, {%4,%5,%6,%7}, {%8,%9}, {%0,%1,%2,%3};"
        : "+f"(c[0]), "+f"(c[1]), "+f"(c[2]), "+f"(c[3])
        : "r"(a[0]), "r"(a[1]), "r"(a[2]), "r"(a[3]), "r"(b0), "r"(b1));
}
__device__ __forceinline__ void ldsm_x4(unsigned& r0, unsigned& r1,
                                        unsigned& r2, unsigned& r3,
                                        unsigned addr) {
    asm volatile(
        "ldmatrix.sync.aligned.m8n8.x4.shared.b16 {%0,%1,%2,%3}, [%4];"
        : "=r"(r0), "=r"(r1), "=r"(r2), "=r"(r3) : "r"(addr));
}

// ---------------------------------------------------------------------------
// Kernel T: sigmoid + hi/lo bf16 split -> mma.sync GEMM, K-split.
// grid(KS, 4 qtiles of 64, 4 batches), 256 thr, 3 CTAs/SM.
// Warp w: wq = w&3 (16-q tile), wd = w>>2 (32-d half of the 64-d chunk).
// A fragments in registers (sigmoid fused); B double-buffered bf16 smem,
// ldmatrix.x4 fragment loads, ONE barrier per chunk (convert||MMA overlap).
// ---------------------------------------------------------------------------
__global__ void __launch_bounds__(256, 3)
kT(const float* __restrict__ pm, const float* __restrict__ gt) {
    __shared__ float    redS[4096];             // 16 KB cross-wd reduction
    __shared__ unsigned bS[2][32 * (BROW / 4)]; // B tiles, double buffered
    __shared__ float    psumS[128];             // [2][64] per-q sigmoid partials

    const int ks = blockIdx.x, qt = blockIdx.y, b = blockIdx.z;
    const int q0 = qt * 64;
    const int tid = threadIdx.x, lane = tid & 31, w = tid >> 5;
    const int wq = w & 3, wd = w >> 2;
    const int gr = lane >> 2, th4 = lane & 3;

    float acc[4][4];
    #pragma unroll
    for (int j = 0; j < 4; j++)
        #pragma unroll
        for (int i = 0; i < 4; i++) acc[j][i] = 0.f;

    float rs0 = 0.f, rs1 = 0.f, gsum = 0.f;

    // B staging map: thread t -> gt row bn = t>>3, 8-d segment at bseg*8
    const int bn = tid >> 3, bseg = tid & 7;
    const float* gtp = gt + (size_t)(b * NGT + bn) * DTOT + bseg * 8;

    // A fragment map: rows qA0 = q0 + wq*16 + gr, qA1 = qA0 + 8
    const int qA0 = q0 + wq * 16 + gr, qA1 = qA0 + 8;
    const bool v0 = qA0 < NQ, v1 = qA1 < NQ;
    const float* pA0 = pm + (size_t)(b * NQ + (v0 ? qA0 : 0)) * DTOT + wd * 32 + th4 * 2;
    const float* pA1 = pm + (size_t)(b * NQ + (v1 ? qA1 : 0)) * DTOT + wd * 32 + th4 * 2;

    // ldmatrix per-lane base: row (lane&7) within j-tile, k-window (lane>>3)*16B
    unsigned lb[2];
    {
        unsigned base = (unsigned)__cvta_generic_to_shared(&bS[0][0]);
        unsigned off = (unsigned)(lane & 7) * BROW + wd * 64 + (unsigned)(lane >> 3) * 16;
        lb[0] = base + off;
        lb[1] = base + 32 * BROW + off;
    }

    const int c0 = (ks * NCH) / KS, c1 = ((ks + 1) * NCH) / KS;

    float2 rA0[2], rA1[2], rA0b[2], rA1b[2];   // kstep s: (qA0,k),(qA1,k),(+8)
    float4 rB[2];

    {   // preload chunk c0
        const int kb = c0 * DCH;
        #pragma unroll
        for (int s = 0; s < 2; s++) {
            if (v0) {
                rA0[s]  = *reinterpret_cast<const float2*>(pA0 + kb + s * 16);
                rA0b[s] = *reinterpret_cast<const float2*>(pA0 + kb + s * 16 + 8);
            }
            if (v1) {
                rA1[s]  = *reinterpret_cast<const float2*>(pA1 + kb + s * 16);
                rA1b[s] = *reinterpret_cast<const float2*>(pA1 + kb + s * 16 + 8);
            }
        }
        rB[0] = *reinterpret_cast<const float4*>(gtp + kb);
        rB[1] = *reinterpret_cast<const float4*>(gtp + kb + 4);
    }

    for (int c = c0; c < c1; c++) {
        const int buf = c & 1;

        // ---- stage B chunk (consumes rB); accumulate gt row sums ----
        {
            float4 va = rB[0], vb = rB[1];
            gsum += (va.x + va.y) + (va.z + va.w) + (vb.x + vb.y) + (vb.z + vb.w);
            __nv_bfloat162 p0 = __floats2bfloat162_rn(va.x, va.y);
            __nv_bfloat162 p1 = __floats2bfloat162_rn(va.z, va.w);
            __nv_bfloat162 p2 = __floats2bfloat162_rn(vb.x, vb.y);
            __nv_bfloat162 p3 = __floats2bfloat162_rn(vb.z, vb.w);
            *reinterpret_cast<uint4*>(
                reinterpret_cast<char*>(bS[buf]) + bn * BROW + bseg * 16) =
                make_uint4(*reinterpret_cast<unsigned*>(&p0),
                           *reinterpret_cast<unsigned*>(&p1),
                           *reinterpret_cast<unsigned*>(&p2),
                           *reinterpret_cast<unsigned*>(&p3));
        }
        // ---- prefetch next B immediately ----
        if (c + 1 < c1) {
            const int kb = (c + 1) * DCH;
            rB[0] = *reinterpret_cast<const float4*>(gtp + kb);
            rB[1] = *reinterpret_cast<const float4*>(gtp + kb + 4);
        }

        // ---- build A fragments: sigmoid + hi/lo split (consumes rA) ----
        unsigned ah[2][4], al[2][4];
        #pragma unroll
        for (int s = 0; s < 2; s++) {
            float x0 = 0.f, x1 = 0.f;
            if (v0) { x0 = sigf(rA0[s].x);  x1 = sigf(rA0[s].y);  rs0 += x0 + x1; }
            split_bf16(x0, x1, ah[s][0], al[s][0]);
            x0 = x1 = 0.f;
            if (v1) { x0 = sigf(rA1[s].x);  x1 = sigf(rA1[s].y);  rs1 += x0 + x1; }
            split_bf16(x0, x1, ah[s][1], al[s][1]);
            x0 = x1 = 0.f;
            if (v0) { x0 = sigf(rA0b[s].x); x1 = sigf(rA0b[s].y); rs0 += x0 + x1; }
            split_bf16(x0, x1, ah[s][2], al[s][2]);
            x0 = x1 = 0.f;
            if (v1) { x0 = sigf(rA1b[s].x); x1 = sigf(rA1b[s].y); rs1 += x0 + x1; }
            split_bf16(x0, x1, ah[s][3], al[s][3]);
        }
        // ---- prefetch next A ----
        if (c + 1 < c1) {
            const int kb = (c + 1) * DCH;
            #pragma unroll
            for (int s = 0; s < 2; s++) {
                if (v0) {
                    rA0[s]  = *reinterpret_cast<const float2*>(pA0 + kb + s * 16);
                    rA0b[s] = *reinterpret_cast<const float2*>(pA0 + kb + s * 16 + 8);
                }
                if (v1) {
                    rA1[s]  = *reinterpret_cast<const float2*>(pA1 + kb + s * 16);
                    rA1b[s] = *reinterpret_cast<const float2*>(pA1 + kb + s * 16 + 8);
                }
            }
        }

        // ---- ONE barrier: bS[buf] published; prior readers done ----
        __syncthreads();

        // ---- MMA: per j-tile one ldmatrix.x4 (2 ksteps), hi+lo ----
        #pragma unroll
        for (int j = 0; j < 4; j++) {
            unsigned b0, b1, b2, b3;
            ldsm_x4(b0, b1, b2, b3, lb[buf] + (unsigned)(j * 8) * BROW);
            mma16816(acc[j], ah[0], b0, b1);
            mma16816(acc[j], al[0], b0, b1);
            mma16816(acc[j], ah[1], b2, b3);
            mma16816(acc[j], al[1], b2, b3);
        }
        // no second barrier: next stage writes bS[buf^1], safe by induction
    }
    __syncthreads();

    // ---- cross-wd reduction (deterministic) ----
    #pragma unroll
    for (int j = 0; j < 4; j++) {
        const int n = j * 8 + th4 * 2;
        redS[wd * 2048 + (wq * 16 + gr) * 32 + n]         = acc[j][0];
        redS[wd * 2048 + (wq * 16 + gr) * 32 + n + 1]     = acc[j][1];
        redS[wd * 2048 + (wq * 16 + gr + 8) * 32 + n]     = acc[j][2];
        redS[wd * 2048 + (wq * 16 + gr + 8) * 32 + n + 1] = acc[j][3];
    }
    // per-q sigmoid sums: reduce over the 4 lanes sharing a q row
    rs0 += __shfl_down_sync(0xffffffffu, rs0, 2);
    rs0 += __shfl_down_sync(0xffffffffu, rs0, 1);
    rs1 += __shfl_down_sync(0xffffffffu, rs1, 2);
    rs1 += __shfl_down_sync(0xffffffffu, rs1, 1);
    if (th4 == 0) {
        psumS[wd * 64 + wq * 16 + gr]     = rs0;
        psumS[wd * 64 + wq * 16 + gr + 8] = rs1;
    }
    __syncthreads();

    for (int o = tid; o < 2048; o += 256) {
        float s = redS[o] + redS[2048 + o];
        int q = o >> 5;
        if (q0 + q < NQ)
            g_part[((size_t)(ks * 4 + b) * NQ + q0 + q) * 32 + (o & 31)] = s;
    }
    if (tid < 64 && q0 + tid < NQ)
        g_psum[(ks * 4 + b) * NQ + q0 + tid] = psumS[tid] + psumS[64 + tid];

    // per-n gt sums (qt==0 only): 8 consecutive threads share row n
    if (qt == 0) {
        gsum += __shfl_down_sync(0xffffffffu, gsum, 4);
        gsum += __shfl_down_sync(0xffffffffu, gsum, 2);
        gsum += __shfl_down_sync(0xffffffffu, gsum, 1);
        if ((tid & 7) == 0)
            g_gtp[(ks * 4 + b) * NGT + (tid >> 3)] = gsum;
    }
}

// ---------------------------------------------------------------------------
// Kernel R: reduce partials -> combined scores. grid(4, 25), 256 thr.
// ---------------------------------------------------------------------------
__global__ void __launch_bounds__(256)
kR(const float* __restrict__ logits) {
    const int b = blockIdx.x, yo = blockIdx.y, tid = threadIdx.x;
    __shared__ float psS[8], clsS[8], gsS[32];

    if (tid < 8) {
        int q = yo * 8 + tid;
        float s = 0.f;
        #pragma unroll
        for (int z = 0; z < KS; z++) s += g_psum[(z * 4 + b) * NQ + q];
        psS[tid] = s;
        float l0 = logits[(b * NQ + q) * 2 + 0];
        float l1 = logits[(b * NQ + q) * 2 + 1];
        clsS[tid] = 1.0f / (1.0f + expf(l0 - l1));   // softmax(...)[1]
    } else if (tid >= 32 && tid < 64) {
        int n = tid - 32;
        float s = 0.f;
        #pragma unroll
        for (int z = 0; z < KS; z++) s += g_gtp[(z * 4 + b) * NGT + n];
        gsS[n] = s;
    }
    __syncthreads();

    const int o = yo * 256 + tid;
    const int q = o >> 5, n = o & 31;
    float inter = 0.f;
    #pragma unroll
    for (int z = 0; z < KS; z++)
        inter += g_part[((size_t)(z * 4 + b) * NQ + q) * 32 + n];
    g_comb[b * NQ * NGT + o] =
        inter / (psS[tid >> 5] + gsS[n] - inter + 1e-6f) * clsS[tid >> 5];
}

// ---------------------------------------------------------------------------
// Kernel C2: per-column top-4 + parallel dedup + output. grid(4), 256 thr.
// OUTPUT is float32: src||tgt||valid as floats (512 each).
// ---------------------------------------------------------------------------
__global__ void __launch_bounds__(256)
kC2(float* __restrict__ out) {
    const int b = blockIdx.x, tid = threadIdx.x;
    __shared__ float comb[NQ * NGT];
    __shared__ int top4[NGT * 4];

    for (int o = tid; o < NQ * NGT; o += 256)
        comb[o] = g_comb[b * NQ * NGT + o];
    __syncthreads();

    const int w = tid >> 5, lane = tid & 31;
    for (int n = w * 4; n < w * 4 + 4; n++) {
        float v[7];
        #pragma unroll
        for (int t = 0; t < 7; t++) {
            int q = lane + 32 * t;
            v[t] = (q < NQ) ? comb[q * 32 + n] : -1e30f;
        }
        unsigned selmask = 0;
        for (int kk = 0; kk < 4; kk++) {
            float bv = -1e30f; int bq = 1 << 20;
            #pragma unroll
            for (int t = 0; t < 7; t++) {
                int q = lane + 32 * t;
                if (!((selmask >> t) & 1) && q < NQ) {
                    if (v[t] > bv || (v[t] == bv && q < bq)) { bv = v[t]; bq = q; }
                }
            }
            for (int off = 16; off; off >>= 1) {
                float ov = __shfl_xor_sync(0xffffffffu, bv, off);
                int   oq = __shfl_xor_sync(0xffffffffu, bq, off);
                if (ov > bv || (ov == bv && oq < bq)) { bv = ov; bq = oq; }
            }
            if (lane == 0) top4[n * 4 + kk] = bq;
            if ((bq & 31) == lane) selmask |= 1u << (bq >> 5);
        }
    }
    __syncthreads();

    if (tid < NGT * 4) {
        int q = top4[tid];
        int n = tid >> 2;
        bool dup = false;
        for (int sp = 0; sp < (n << 2); sp++) dup |= (top4[sp] == q);
        int sel = dup ? -1 : q;
        int o = (b * NGT + n) * 4 + (tid & 3);
        out[o]        = (float)sel;
        out[512 + o]  = (sel >= 0) ? (float)n : -1.0f;
        out[1024 + o] = (sel >= 0) ? 1.0f : 0.0f;
    }
}

extern "C" void kernel_launch(void* const* d_in, const int* in_sizes, int n_in,
                              void* d_out, int out_size) {
    const float* pm = (const float*)d_in[0];   // [4,200,256,256]
    const float* lg = (const float*)d_in[1];   // [4,200,2]
    const float* gt = (const float*)d_in[2];   // [4,32,256,256]
    float* out = (float*)d_out;

    kT<<<dim3(KS, 4, 4), 256>>>(pm, gt);
    kR<<<dim3(4, 25), 256>>>(lg);
    kC2<<<4, 256>>>(out);
}